// round 9
// baseline (speedup 1.0000x reference)
#include <cuda_runtime.h>
#include <cuda_fp16.h>
#include <cstdint>

// ============================================================================
// QConv2D quantum conv via baseline-PTX fp16 mma.sync (HMMA) GEMM.
//   Kernel 1: build 64x64 unitary U (register statevector, warp per column).
//   B[128x64] fp16, rows interleaved: B[2s]=Re U[s,:], B[2s+1]=Im U[s,:].
//   Kernel 2: persistent CTA over 7 tiles x 128 patches. cp.async double-
//   buffers raw x (gmem->smem) under the GEMM. Per tile: convert to fp16 A,
//   C[128x128] = A*B^T (fp32 accum), probs, Walsh sums, deferred norm.
// ============================================================================

#define N_QUBITS 6
#define OH 63
#define OHW 3969
#define NPATCH (128 * OHW)     // 508032
#define TPC 7
#define GRID 567               // 567 * 7 * 128 = 508032
#define SWZ(o) ((o) ^ (((o) >> 3) & 0x70))

__device__ __half g_B[128 * 64];

__device__ __forceinline__ uint32_t smem_u32(const void* p) {
    uint32_t a;
    asm("{ .reg .u64 t; cvta.to.shared.u64 t, %1; cvt.u32.u64 %0, t; }"
        : "=r"(a) : "l"(p));
    return a;
}
__device__ __forceinline__ void ldmx4(uint32_t* r, uint32_t addr) {
    asm volatile("ldmatrix.sync.aligned.m8n8.x4.shared.b16 {%0,%1,%2,%3}, [%4];"
                 : "=r"(r[0]), "=r"(r[1]), "=r"(r[2]), "=r"(r[3]) : "r"(addr));
}
__device__ __forceinline__ void mma_f16(float* c, const uint32_t* a, const uint32_t* b) {
    asm volatile(
        "mma.sync.aligned.m16n8k16.row.col.f32.f16.f16.f32 "
        "{%0,%1,%2,%3}, {%4,%5,%6,%7}, {%8,%9}, {%0,%1,%2,%3};"
        : "+f"(c[0]), "+f"(c[1]), "+f"(c[2]), "+f"(c[3])
        : "r"(a[0]), "r"(a[1]), "r"(a[2]), "r"(a[3]), "r"(b[0]), "r"(b[1]));
}
#define CP_ASYNC8(dst, src) \
    asm volatile("cp.async.ca.shared.global [%0], [%1], 8;" :: "r"(dst), "l"(src) : "memory")
#define CP_COMMIT() asm volatile("cp.async.commit_group;" ::: "memory")
#define CP_WAIT1()  asm volatile("cp.async.wait_group 1;" ::: "memory")

__device__ __forceinline__ float2 cmad(float2 u, float2 a, float2 v, float2 b) {
    float2 r;
    r.x = u.x * a.x - u.y * a.y + v.x * b.x - v.y * b.y;
    r.y = u.x * a.y + u.y * a.x + v.x * b.y + v.y * b.x;
    return r;
}

// ----------------------------------------------------------------------------
// Kernel 1: build U. One warp per column; lane holds states 2L, 2L+1.
// ----------------------------------------------------------------------------
__global__ __launch_bounds__(256) void build_unitary_kernel(const float* __restrict__ w) {
    __shared__ float gt[12][8];
    const int t = threadIdx.x;
    if (t < 12) {
        int l = t / 6, q = t % 6;
        float phi   = w[(l * 6 + q) * 3 + 0];
        float theta = w[(l * 6 + q) * 3 + 1];
        float omega = w[(l * 6 + q) * 3 + 2];
        float s2, c2; sincosf(0.5f * theta, &s2, &c2);
        float sap, cap; sincosf(-0.5f * (phi + omega), &sap, &cap);
        float sam, cam; sincosf(-0.5f * (phi - omega), &sam, &cam);
        gt[t][0] =  cap * c2; gt[t][1] =  sap * c2;
        gt[t][2] = -cam * s2; gt[t][3] =  sam * s2;
        gt[t][4] =  cam * s2; gt[t][5] =  sam * s2;
        gt[t][6] =  cap * c2; gt[t][7] = -sap * c2;
    }
    __syncthreads();

    const int lane = t & 31;
    const int col  = blockIdx.x * 8 + (t >> 5);

    float2 s0 = make_float2((2 * lane     == col) ? 1.f : 0.f, 0.f);
    float2 s1 = make_float2((2 * lane + 1 == col) ? 1.f : 0.f, 0.f);

    for (int rep = 0; rep < 2; rep++) {
        for (int l = 0; l < 2; l++) {
            for (int q = 0; q < N_QUBITS; q++) {
                const float* g = gt[l * 6 + q];
                float2 u00 = {g[0], g[1]}, u01 = {g[2], g[3]};
                float2 u10 = {g[4], g[5]}, u11 = {g[6], g[7]};
                int m = 1 << (5 - q);
                if (m == 1) {
                    float2 a = s0, b = s1;
                    s0 = cmad(u00, a, u01, b);
                    s1 = cmad(u10, a, u11, b);
                } else {
                    int d = m >> 1;
                    float2 p0, p1;
                    p0.x = __shfl_xor_sync(0xffffffffu, s0.x, d);
                    p0.y = __shfl_xor_sync(0xffffffffu, s0.y, d);
                    p1.x = __shfl_xor_sync(0xffffffffu, s1.x, d);
                    p1.y = __shfl_xor_sync(0xffffffffu, s1.y, d);
                    if (lane & d) {
                        s0 = cmad(u10, p0, u11, s0);
                        s1 = cmad(u10, p1, u11, s1);
                    } else {
                        s0 = cmad(u00, s0, u01, p0);
                        s1 = cmad(u00, s1, u01, p1);
                    }
                }
            }
            int r = l + 1;
            for (int q = 0; q < N_QUBITS; q++) {
                int tq = (q + r) % N_QUBITS;
                int mc = 1 << (5 - q);
                int mt = 1 << (5 - tq);
                if (mt == 1) {
                    if (lane & (mc >> 1)) { float2 tmp = s0; s0 = s1; s1 = tmp; }
                } else {
                    int d = mt >> 1;
                    if (mc == 1) {
                        float2 t1;
                        t1.x = __shfl_xor_sync(0xffffffffu, s1.x, d);
                        t1.y = __shfl_xor_sync(0xffffffffu, s1.y, d);
                        s1 = t1;
                    } else {
                        float2 t0, t1;
                        t0.x = __shfl_xor_sync(0xffffffffu, s0.x, d);
                        t0.y = __shfl_xor_sync(0xffffffffu, s0.y, d);
                        t1.x = __shfl_xor_sync(0xffffffffu, s1.x, d);
                        t1.y = __shfl_xor_sync(0xffffffffu, s1.y, d);
                        if (lane & (mc >> 1)) { s0 = t0; s1 = t1; }
                    }
                }
            }
        }
    }
    g_B[(4 * lane + 0) * 64 + col] = __float2half(s0.x);
    g_B[(4 * lane + 1) * 64 + col] = __float2half(s0.y);
    g_B[(4 * lane + 2) * 64 + col] = __float2half(s1.x);
    g_B[(4 * lane + 3) * 64 + col] = __float2half(s1.y);
}

// ----------------------------------------------------------------------------
// Kernel 2
// ----------------------------------------------------------------------------
#define XPITCH 272               // raw x: bytes per patch (64 f32 + 16B pad)
#define SM_B   0                 // 16 KB
#define SM_A   16384             // 16 KB
#define SM_X0  32768             // 34816 B
#define SM_X1  67584             // 34816 B
#define SM_SSQ 102400            // 512 B
#define SM_SZ  102912            // 6144 B
#define SM_TOTAL 109056

__global__ __launch_bounds__(256, 2)
void qconv_kernel(const float* __restrict__ x, float* __restrict__ out) {
    extern __shared__ char smem[];
    const uint32_t sb = smem_u32(smem);
    float* sSsq = reinterpret_cast<float*>(smem + SM_SSQ);
    float* sZ   = reinterpret_cast<float*>(smem + SM_SZ);   // [ni][row][6]
    const int tid = threadIdx.x;
    const int p   = tid >> 1;            // patch within tile
    const int h   = tid & 1;             // channel-pair half
    const int base = blockIdx.x * (TPC * 128);

    // ---- gather issue: 16x 8B cp.async for this thread's half-patch ----
    auto issue_gather = [&](int t, uint32_t xoff) {
        const int pi  = base + t * 128 + p;
        const int b   = pi / OHW;
        const int rem = pi - b * OHW;
        const int oy  = rem / OH;
        const int ox  = rem - oy * OH;
        const float* xb = x + (((b * 4 + 2 * h) * 128) + 2 * oy) * 128 + 2 * ox;
        const uint32_t dbase = sb + xoff + (uint32_t)(p * XPITCH + h * 128);
        #pragma unroll
        for (int c2 = 0; c2 < 2; c2++)
            #pragma unroll
            for (int ky = 0; ky < 4; ky++) {
                const float* s = xb + c2 * 16384 + ky * 128;
                uint32_t d = dbase + (uint32_t)((c2 * 16 + ky * 4) * 4);
                CP_ASYNC8(d, s);
                CP_ASYNC8(d + 8, s + 2);
            }
    };

    // ---- B gmem loads (once) ----
    uint4 breg[4];
    {
        const uint4* bsrc = reinterpret_cast<const uint4*>(g_B);
        #pragma unroll
        for (int it = 0; it < 4; it++) breg[it] = bsrc[tid + it * 256];
    }

    issue_gather(0, SM_X0); CP_COMMIT();
    issue_gather(1, SM_X1); CP_COMMIT();

    // ---- stage B with swizzle (once) ----
    #pragma unroll
    for (int it = 0; it < 4; it++) {
        uint32_t off = SWZ((uint32_t)((tid + it * 256) * 16));
        *reinterpret_cast<uint4*>(smem + SM_B + off) = breg[it];
    }

    CP_WAIT1();              // tile 0 raw x ready
    __syncthreads();

    // ---- GEMM constants ----
    const int L   = tid & 31;
    const int wid = tid >> 5;
    const int mi  = wid >> 1;
    const int ni  = wid & 1;
    const int Rm  = mi * 32;
    const int Cn  = ni * 64;
    const int g   = L >> 2;
    const int qd  = L & 3;
    const uint32_t aRow = (uint32_t)(Rm + (L & 7) + (((L >> 3) & 1) << 3));
    const uint32_t aCh  = (L >> 4) & 1;
    const uint32_t bRow = (uint32_t)(Cn + (L & 7) + (((L >> 4) & 1) << 3));
    const uint32_t bCh  = (L >> 3) & 1;

    for (int t = 0; t < TPC; t++) {
        const uint32_t xoff = (t & 1) ? SM_X1 : SM_X0;

        // ---- convert raw x -> fp16 A smem + ssq ----
        {
            const char* rb = smem + xoff + p * XPITCH + h * 128;
            float ssq = 0.f;
            #pragma unroll
            for (int c2 = 0; c2 < 2; c2++)
                #pragma unroll
                for (int ky2 = 0; ky2 < 2; ky2++) {
                    float4 q0 = *reinterpret_cast<const float4*>(rb + (c2 * 16 + 2 * ky2 * 4) * 4);
                    float4 q1 = *reinterpret_cast<const float4*>(rb + (c2 * 16 + (2 * ky2 + 1) * 4) * 4);
                    ssq += q0.x * q0.x + q0.y * q0.y + q0.z * q0.z + q0.w * q0.w;
                    ssq += q1.x * q1.x + q1.y * q1.y + q1.z * q1.z + q1.w * q1.w;
                    __half2 h0 = __float22half2_rn(make_float2(q0.x, q0.y));
                    __half2 h1 = __float22half2_rn(make_float2(q0.z, q0.w));
                    __half2 h2 = __float22half2_rn(make_float2(q1.x, q1.y));
                    __half2 h3 = __float22half2_rn(make_float2(q1.z, q1.w));
                    int chunk = h * 4 + c2 * 2 + ky2;
                    uint32_t off = SWZ((uint32_t)(p * 128 + chunk * 16));
                    *reinterpret_cast<uint4*>(smem + SM_A + off) =
                        make_uint4(*reinterpret_cast<uint32_t*>(&h0),
                                   *reinterpret_cast<uint32_t*>(&h1),
                                   *reinterpret_cast<uint32_t*>(&h2),
                                   *reinterpret_cast<uint32_t*>(&h3));
                }
            ssq += __shfl_xor_sync(0xffffffffu, ssq, 1);
            if (h == 0) sSsq[p] = ssq;
        }
        __syncthreads();

        // ---- issue gather for tile t+2 into the buffer just consumed ----
        if (t + 2 < TPC) issue_gather(t + 2, xoff);
        CP_COMMIT();

        // ---- GEMM ----
        float acc[2][8][4];
        #pragma unroll
        for (int mt = 0; mt < 2; mt++)
            #pragma unroll
            for (int nt = 0; nt < 8; nt++)
                #pragma unroll
                for (int r = 0; r < 4; r++) acc[mt][nt][r] = 0.f;

        #pragma unroll
        for (int k = 0; k < 4; k++) {
            uint32_t ah[2][4];
            #pragma unroll
            for (int mt = 0; mt < 2; mt++) {
                uint32_t off = SWZ((aRow + mt * 16) * 128 + (2 * k + aCh) * 16);
                ldmx4(ah[mt], sb + SM_A + off);
            }
            #pragma unroll
            for (int bt = 0; bt < 4; bt++) {
                uint32_t off = SWZ((bRow + bt * 16) * 128 + (2 * k + bCh) * 16);
                uint32_t bf[4];
                ldmx4(bf, sb + SM_B + off);
                #pragma unroll
                for (int mt = 0; mt < 2; mt++)
                    #pragma unroll
                    for (int n2 = 0; n2 < 2; n2++) {
                        int nt = bt * 2 + n2;
                        mma_f16(acc[mt][nt], ah[mt], bf + 2 * n2);
                    }
            }
        }

        // ---- epilogue: state s = 32ni + 4nt + qd ----
        #pragma unroll
        for (int mt = 0; mt < 2; mt++) {
            #pragma unroll
            for (int rh = 0; rh < 2; rh++) {
                float pr[8];
                #pragma unroll
                for (int nt = 0; nt < 8; nt++) {
                    float re = acc[mt][nt][rh * 2 + 0];
                    float im = acc[mt][nt][rh * 2 + 1];
                    pr[nt] = re * re + im * im;
                }
                float qt = 0.f, z1 = 0.f, z2 = 0.f, z3 = 0.f;
                #pragma unroll
                for (int nt = 0; nt < 8; nt++) {
                    qt += pr[nt];
                    z1 += (nt & 4) ? -pr[nt] : pr[nt];
                    z2 += (nt & 2) ? -pr[nt] : pr[nt];
                    z3 += (nt & 1) ? -pr[nt] : pr[nt];
                }
                float W = qt;
                #pragma unroll
                for (int m = 1; m <= 2; m <<= 1) {
                    float tt = __shfl_xor_sync(0xffffffffu, W, m);
                    W = (L & m) ? (tt - W) : (W + tt);
                }
                z1 += __shfl_xor_sync(0xffffffffu, z1, 1);
                z1 += __shfl_xor_sync(0xffffffffu, z1, 2);
                z2 += __shfl_xor_sync(0xffffffffu, z2, 1);
                z2 += __shfl_xor_sync(0xffffffffu, z2, 2);
                z3 += __shfl_xor_sync(0xffffffffu, z3, 1);
                z3 += __shfl_xor_sync(0xffffffffu, z3, 2);

                int row = Rm + mt * 16 + rh * 8 + g;
                float* dst = sZ + (ni * 128 + row) * 6;
                if (qd == 0) { dst[0] = W; dst[1] = z1; dst[2] = z2; dst[3] = z3; }
                else if (qd == 1) dst[5] = W;
                else if (qd == 2) dst[4] = W;
            }
        }
        __syncthreads();

        // ---- merge halves + normalize + store ----
        if (tid < 128) {
            const int row = tid;
            const int pi  = base + t * 128 + row;
            const int b   = pi / OHW;
            const int rem = pi - b * OHW;
            const float inv = 1.f / sSsq[row];
            const float* p0 = sZ + row * 6;
            const float* p1 = sZ + (128 + row) * 6;
            out[(b * 6 + 0) * OHW + rem] = (p0[0] - p1[0]) * inv;
            #pragma unroll
            for (int w = 1; w < 6; w++)
                out[(b * 6 + w) * OHW + rem] = (p0[w] + p1[w]) * inv;
        }

        if (t + 1 < TPC) {
            CP_WAIT1();          // next tile's raw x ready
            __syncthreads();
        }
    }
}

// ----------------------------------------------------------------------------
extern "C" void kernel_launch(void* const* d_in, const int* in_sizes, int n_in,
                              void* d_out, int out_size) {
    const float* x = (const float*)d_in[0];      // (128, 4, 128, 128) f32
    const float* w = (const float*)d_in[1];      // (2, 6, 3) f32
    float* out = (float*)d_out;                  // (128, 6, 63, 63) f32
    (void)in_sizes; (void)n_in; (void)out_size;

    cudaFuncSetAttribute(qconv_kernel, cudaFuncAttributeMaxDynamicSharedMemorySize, SM_TOTAL);
    build_unitary_kernel<<<8, 256>>>(w);
    qconv_kernel<<<GRID, 256, SM_TOTAL>>>(x, out);
}

// round 10
// speedup vs baseline: 1.0752x; 1.0752x over previous
#include <cuda_runtime.h>
#include <cuda_fp16.h>
#include <cstdint>

// ============================================================================
// QConv2D quantum conv via baseline-PTX fp16 mma.sync (HMMA) GEMM.
//   Kernel 1: build 64x64 unitary U (register statevector, warp per column).
//   B[128x64] fp16, rows interleaved: B[2s]=Re U[s,:], B[2s+1]=Im U[s,:].
//   Kernel 2 (CTA = 128 patches): A = patch features fp16,
//   C[128x128] = A*B^T (fp32 accum). Epilogue: probs, factorized in-register
//   Walsh (18-add) + quad butterflies, deferred normalization by ||f||^2.
// ============================================================================

#define N_QUBITS 6
#define OH 63
#define OHW 3969
#define NPATCH (128 * OHW)     // 508032
#define SWZ(o) ((o) ^ (((o) >> 3) & 0x70))

__device__ __half g_B[128 * 64];

__device__ __forceinline__ uint32_t smem_u32(const void* p) {
    uint32_t a;
    asm("{ .reg .u64 t; cvta.to.shared.u64 t, %1; cvt.u32.u64 %0, t; }"
        : "=r"(a) : "l"(p));
    return a;
}
__device__ __forceinline__ void ldmx4(uint32_t* r, uint32_t addr) {
    asm volatile("ldmatrix.sync.aligned.m8n8.x4.shared.b16 {%0,%1,%2,%3}, [%4];"
                 : "=r"(r[0]), "=r"(r[1]), "=r"(r[2]), "=r"(r[3]) : "r"(addr));
}
__device__ __forceinline__ void mma_f16(float* c, const uint32_t* a, const uint32_t* b) {
    asm volatile(
        "mma.sync.aligned.m16n8k16.row.col.f32.f16.f16.f32 "
        "{%0,%1,%2,%3}, {%4,%5,%6,%7}, {%8,%9}, {%0,%1,%2,%3};"
        : "+f"(c[0]), "+f"(c[1]), "+f"(c[2]), "+f"(c[3])
        : "r"(a[0]), "r"(a[1]), "r"(a[2]), "r"(a[3]), "r"(b[0]), "r"(b[1]));
}
__device__ __forceinline__ float2 cmad(float2 u, float2 a, float2 v, float2 b) {
    float2 r;
    r.x = u.x * a.x - u.y * a.y + v.x * b.x - v.y * b.y;
    r.y = u.x * a.y + u.y * a.x + v.x * b.y + v.y * b.x;
    return r;
}

// ----------------------------------------------------------------------------
// Kernel 1: build U. One warp per column; lane holds states 2L, 2L+1.
// grid=8, block=256 (8 warps) -> 64 columns.
// ----------------------------------------------------------------------------
__global__ __launch_bounds__(256) void build_unitary_kernel(const float* __restrict__ w) {
    __shared__ float gt[12][8];
    const int t = threadIdx.x;
    if (t < 12) {
        int l = t / 6, q = t % 6;
        float phi   = w[(l * 6 + q) * 3 + 0];
        float theta = w[(l * 6 + q) * 3 + 1];
        float omega = w[(l * 6 + q) * 3 + 2];
        float s2, c2; sincosf(0.5f * theta, &s2, &c2);
        float sap, cap; sincosf(-0.5f * (phi + omega), &sap, &cap);
        float sam, cam; sincosf(-0.5f * (phi - omega), &sam, &cam);
        gt[t][0] =  cap * c2; gt[t][1] =  sap * c2;   // u00
        gt[t][2] = -cam * s2; gt[t][3] =  sam * s2;   // u01
        gt[t][4] =  cam * s2; gt[t][5] =  sam * s2;   // u10
        gt[t][6] =  cap * c2; gt[t][7] = -sap * c2;   // u11
    }
    __syncthreads();

    const int lane = t & 31;
    const int col  = blockIdx.x * 8 + (t >> 5);

    float2 s0 = make_float2((2 * lane     == col) ? 1.f : 0.f, 0.f);
    float2 s1 = make_float2((2 * lane + 1 == col) ? 1.f : 0.f, 0.f);

    for (int rep = 0; rep < 2; rep++) {
        for (int l = 0; l < 2; l++) {
            for (int q = 0; q < N_QUBITS; q++) {
                const float* g = gt[l * 6 + q];
                float2 u00 = {g[0], g[1]}, u01 = {g[2], g[3]};
                float2 u10 = {g[4], g[5]}, u11 = {g[6], g[7]};
                int m = 1 << (5 - q);
                if (m == 1) {
                    float2 a = s0, b = s1;
                    s0 = cmad(u00, a, u01, b);
                    s1 = cmad(u10, a, u11, b);
                } else {
                    int d = m >> 1;
                    float2 p0, p1;
                    p0.x = __shfl_xor_sync(0xffffffffu, s0.x, d);
                    p0.y = __shfl_xor_sync(0xffffffffu, s0.y, d);
                    p1.x = __shfl_xor_sync(0xffffffffu, s1.x, d);
                    p1.y = __shfl_xor_sync(0xffffffffu, s1.y, d);
                    if (lane & d) {
                        s0 = cmad(u10, p0, u11, s0);
                        s1 = cmad(u10, p1, u11, s1);
                    } else {
                        s0 = cmad(u00, s0, u01, p0);
                        s1 = cmad(u00, s1, u01, p1);
                    }
                }
            }
            int r = l + 1;
            for (int q = 0; q < N_QUBITS; q++) {
                int tq = (q + r) % N_QUBITS;
                int mc = 1 << (5 - q);
                int mt = 1 << (5 - tq);
                if (mt == 1) {
                    if (lane & (mc >> 1)) { float2 tmp = s0; s0 = s1; s1 = tmp; }
                } else {
                    int d = mt >> 1;
                    if (mc == 1) {
                        float2 t1;
                        t1.x = __shfl_xor_sync(0xffffffffu, s1.x, d);
                        t1.y = __shfl_xor_sync(0xffffffffu, s1.y, d);
                        s1 = t1;
                    } else {
                        float2 t0, t1;
                        t0.x = __shfl_xor_sync(0xffffffffu, s0.x, d);
                        t0.y = __shfl_xor_sync(0xffffffffu, s0.y, d);
                        t1.x = __shfl_xor_sync(0xffffffffu, s1.x, d);
                        t1.y = __shfl_xor_sync(0xffffffffu, s1.y, d);
                        if (lane & (mc >> 1)) { s0 = t0; s1 = t1; }
                    }
                }
            }
        }
    }
    g_B[(4 * lane + 0) * 64 + col] = __float2half(s0.x);
    g_B[(4 * lane + 1) * 64 + col] = __float2half(s0.y);
    g_B[(4 * lane + 2) * 64 + col] = __float2half(s1.x);
    g_B[(4 * lane + 3) * 64 + col] = __float2half(s1.y);
}

// ----------------------------------------------------------------------------
// Kernel 2: HMMA GEMM + epilogue. 256 threads (8 warps, 4x2 tile grid).
// ----------------------------------------------------------------------------
#define SM_A  0            // 16 KB: 128 rows x 128 B
#define SM_B  16384        // 16 KB
#define SM_SSQ 32768       // float[128] = 512 B
#define SM_SZ  33280       // float[2][128][6] = 6144 B
#define SM_TOTAL 39424

__global__ __launch_bounds__(256, 2)
void qconv_kernel(const float* __restrict__ x, float* __restrict__ out) {
    extern __shared__ char smem[];
    const uint32_t sb = smem_u32(smem);
    float* sSsq = reinterpret_cast<float*>(smem + SM_SSQ);
    float* sZ   = reinterpret_cast<float*>(smem + SM_SZ);   // [ni][row][6]
    const int tid = threadIdx.x;

    // ---- B gmem loads first (latency overlaps x gather) ----
    uint4 breg[4];
    {
        const uint4* bsrc = reinterpret_cast<const uint4*>(g_B);
        #pragma unroll
        for (int it = 0; it < 4; it++) breg[it] = bsrc[tid + it * 256];
    }

    // ---- load phase: thread = (patch p = tid>>1, half h = tid&1 -> 2 channels)
    {
        const int p  = tid >> 1;
        const int h  = tid & 1;
        const int pi = blockIdx.x * 128 + p;
        const int b   = pi / OHW;
        const int rem = pi - b * OHW;
        const int oy  = rem / OH;
        const int ox  = rem - oy * OH;
        const float* xb = x + (((b * 4 + 2 * h) * 128) + 2 * oy) * 128 + 2 * ox;

        float ssq = 0.f;
        #pragma unroll
        for (int c2 = 0; c2 < 2; c2++) {
            #pragma unroll
            for (int ky2 = 0; ky2 < 2; ky2++) {
                const float* rA = xb + c2 * 16384 + (2 * ky2) * 128;
                float2 P[4];
                P[0] = *reinterpret_cast<const float2*>(rA);
                P[1] = *reinterpret_cast<const float2*>(rA + 2);
                P[2] = *reinterpret_cast<const float2*>(rA + 128);
                P[3] = *reinterpret_cast<const float2*>(rA + 130);
                uint32_t hw[4];
                #pragma unroll
                for (int j = 0; j < 4; j++) {
                    ssq += P[j].x * P[j].x + P[j].y * P[j].y;
                    __half2 h2 = __float22half2_rn(P[j]);
                    hw[j] = *reinterpret_cast<uint32_t*>(&h2);
                }
                int chunk = h * 4 + c2 * 2 + ky2;
                uint32_t off = SWZ((uint32_t)(p * 128 + chunk * 16));
                *reinterpret_cast<uint4*>(smem + SM_A + off) = make_uint4(hw[0], hw[1], hw[2], hw[3]);
            }
        }
        ssq += __shfl_xor_sync(0xffffffffu, ssq, 1);
        if (h == 0) sSsq[p] = ssq;
    }

    // ---- stage B (fp16) with swizzle ----
    {
        #pragma unroll
        for (int it = 0; it < 4; it++) {
            uint32_t off = SWZ((uint32_t)((tid + it * 256) * 16));
            *reinterpret_cast<uint4*>(smem + SM_B + off) = breg[it];
        }
    }
    __syncthreads();

    // ---- GEMM: warp (mi,ni): rows [32mi,32mi+32), cols [64ni,64ni+64) ----
    const int L   = tid & 31;
    const int wid = tid >> 5;
    const int mi  = wid >> 1;
    const int ni  = wid & 1;
    const int Rm  = mi * 32;
    const int Cn  = ni * 64;
    const int g   = L >> 2;
    const int qd  = L & 3;

    const uint32_t aRow = (uint32_t)(Rm + (L & 7) + (((L >> 3) & 1) << 3));
    const uint32_t aCh  = (L >> 4) & 1;
    const uint32_t bRow = (uint32_t)(Cn + (L & 7) + (((L >> 4) & 1) << 3));
    const uint32_t bCh  = (L >> 3) & 1;

    float acc[2][8][4];
    #pragma unroll
    for (int mt = 0; mt < 2; mt++)
        #pragma unroll
        for (int nt = 0; nt < 8; nt++)
            #pragma unroll
            for (int r = 0; r < 4; r++) acc[mt][nt][r] = 0.f;

    #pragma unroll
    for (int k = 0; k < 4; k++) {
        uint32_t ah[2][4];
        #pragma unroll
        for (int mt = 0; mt < 2; mt++) {
            uint32_t off = SWZ((aRow + mt * 16) * 128 + (2 * k + aCh) * 16);
            ldmx4(ah[mt], sb + SM_A + off);
        }
        #pragma unroll
        for (int bt = 0; bt < 4; bt++) {
            uint32_t off = SWZ((bRow + bt * 16) * 128 + (2 * k + bCh) * 16);
            uint32_t bf[4];
            ldmx4(bf, sb + SM_B + off);
            #pragma unroll
            for (int mt = 0; mt < 2; mt++)
                #pragma unroll
                for (int n2 = 0; n2 < 2; n2++) {
                    int nt = bt * 2 + n2;
                    mma_f16(acc[mt][nt], ah[mt], bf + 2 * n2);
                }
        }
    }

    // ---- epilogue: per thread 4 rows; state s = 32ni + 4nt + qd ----
    // Factorized Walsh over nt (bits: nt&4 -> z1, nt&2 -> z2, nt&1 -> z3).
    #pragma unroll
    for (int mt = 0; mt < 2; mt++) {
        #pragma unroll
        for (int rh = 0; rh < 2; rh++) {
            float pr[8];
            #pragma unroll
            for (int nt = 0; nt < 8; nt++) {
                float re = acc[mt][nt][rh * 2 + 0];
                float im = acc[mt][nt][rh * 2 + 1];
                pr[nt] = re * re + im * im;
            }
            float e0 = pr[0] + pr[4], e1 = pr[1] + pr[5];
            float e2 = pr[2] + pr[6], e3 = pr[3] + pr[7];
            float d0 = pr[0] - pr[4], d1 = pr[1] - pr[5];
            float d2 = pr[2] - pr[6], d3 = pr[3] - pr[7];
            float z1 = (d0 + d1) + (d2 + d3);
            float f0 = e0 + e2, f1 = e1 + e3;
            float qt = f0 + f1;
            float z3 = f0 - f1;
            float z2 = (e0 - e2) + (e1 - e3);

            // signed 4-pt Walsh butterfly over the quad:
            // lane qd=0 -> z0 partial, qd=1 -> z5 partial, qd=2 -> z4 partial
            float W = qt;
            #pragma unroll
            for (int m = 1; m <= 2; m <<= 1) {
                float tt = __shfl_xor_sync(0xffffffffu, W, m);
                W = (L & m) ? (tt - W) : (W + tt);
            }
            z1 += __shfl_xor_sync(0xffffffffu, z1, 1);
            z1 += __shfl_xor_sync(0xffffffffu, z1, 2);
            z2 += __shfl_xor_sync(0xffffffffu, z2, 1);
            z2 += __shfl_xor_sync(0xffffffffu, z2, 2);
            z3 += __shfl_xor_sync(0xffffffffu, z3, 1);
            z3 += __shfl_xor_sync(0xffffffffu, z3, 2);

            int row = Rm + mt * 16 + rh * 8 + g;
            float* dst = sZ + (ni * 128 + row) * 6;
            if (qd == 0) { dst[0] = W; dst[1] = z1; dst[2] = z2; dst[3] = z3; }
            else if (qd == 1) dst[5] = W;
            else if (qd == 2) dst[4] = W;
        }
    }
    __syncthreads();

    // ---- merge halves + normalize + store ----
    if (tid < 128) {
        const int row = tid;
        const int pi  = blockIdx.x * 128 + row;
        const int b   = pi / OHW;
        const int rem = pi - b * OHW;
        const float inv = 1.f / sSsq[row];
        const float* p0 = sZ + row * 6;
        const float* p1 = sZ + (128 + row) * 6;
        out[(b * 6 + 0) * OHW + rem] = (p0[0] - p1[0]) * inv;
        #pragma unroll
        for (int w = 1; w < 6; w++)
            out[(b * 6 + w) * OHW + rem] = (p0[w] + p1[w]) * inv;
    }
}

// ----------------------------------------------------------------------------
extern "C" void kernel_launch(void* const* d_in, const int* in_sizes, int n_in,
                              void* d_out, int out_size) {
    const float* x = (const float*)d_in[0];      // (128, 4, 128, 128) f32
    const float* w = (const float*)d_in[1];      // (2, 6, 3) f32
    float* out = (float*)d_out;                  // (128, 6, 63, 63) f32
    (void)in_sizes; (void)n_in; (void)out_size;

    cudaFuncSetAttribute(qconv_kernel, cudaFuncAttributeMaxDynamicSharedMemorySize, SM_TOTAL);
    build_unitary_kernel<<<8, 256>>>(w);
    qconv_kernel<<<NPATCH / 128, 256, SM_TOTAL>>>(x, out);
}

// round 11
// speedup vs baseline: 1.1245x; 1.0458x over previous
#include <cuda_runtime.h>
#include <cuda_fp16.h>
#include <cstdint>

// ============================================================================
// QConv2D quantum conv via baseline-PTX fp16 mma.sync (HMMA) GEMM.
//   Kernel 1: build 64x64 unitary U (register statevector, warp per column).
//   B[128x64] fp16, rows interleaved: B[2s]=Re U[s,:], B[2s+1]=Im U[s,:].
//   Kernel 2 (CTA = 64 patches, 128 threads, 4 CTAs/SM): A = patch fp16,
//   C[64x128] = A*B^T (fp32 accum). Epilogue: probs, factorized Walsh,
//   deferred normalization by ||f||^2.
// ============================================================================

#define N_QUBITS 6
#define OH 63
#define OHW 3969
#define NPATCH (128 * OHW)     // 508032
#define SWZ(o) ((o) ^ (((o) >> 3) & 0x70))

__device__ __half g_B[128 * 64];

__device__ __forceinline__ uint32_t smem_u32(const void* p) {
    uint32_t a;
    asm("{ .reg .u64 t; cvta.to.shared.u64 t, %1; cvt.u32.u64 %0, t; }"
        : "=r"(a) : "l"(p));
    return a;
}
__device__ __forceinline__ void ldmx4(uint32_t* r, uint32_t addr) {
    asm volatile("ldmatrix.sync.aligned.m8n8.x4.shared.b16 {%0,%1,%2,%3}, [%4];"
                 : "=r"(r[0]), "=r"(r[1]), "=r"(r[2]), "=r"(r[3]) : "r"(addr));
}
__device__ __forceinline__ void mma_f16(float* c, const uint32_t* a, const uint32_t* b) {
    asm volatile(
        "mma.sync.aligned.m16n8k16.row.col.f32.f16.f16.f32 "
        "{%0,%1,%2,%3}, {%4,%5,%6,%7}, {%8,%9}, {%0,%1,%2,%3};"
        : "+f"(c[0]), "+f"(c[1]), "+f"(c[2]), "+f"(c[3])
        : "r"(a[0]), "r"(a[1]), "r"(a[2]), "r"(a[3]), "r"(b[0]), "r"(b[1]));
}
__device__ __forceinline__ float2 cmad(float2 u, float2 a, float2 v, float2 b) {
    float2 r;
    r.x = u.x * a.x - u.y * a.y + v.x * b.x - v.y * b.y;
    r.y = u.x * a.y + u.y * a.x + v.x * b.y + v.y * b.x;
    return r;
}

// ----------------------------------------------------------------------------
// Kernel 1: build U. One warp per column; lane holds states 2L, 2L+1.
// ----------------------------------------------------------------------------
__global__ __launch_bounds__(256) void build_unitary_kernel(const float* __restrict__ w) {
    __shared__ float gt[12][8];
    const int t = threadIdx.x;
    if (t < 12) {
        int l = t / 6, q = t % 6;
        float phi   = w[(l * 6 + q) * 3 + 0];
        float theta = w[(l * 6 + q) * 3 + 1];
        float omega = w[(l * 6 + q) * 3 + 2];
        float s2, c2; sincosf(0.5f * theta, &s2, &c2);
        float sap, cap; sincosf(-0.5f * (phi + omega), &sap, &cap);
        float sam, cam; sincosf(-0.5f * (phi - omega), &sam, &cam);
        gt[t][0] =  cap * c2; gt[t][1] =  sap * c2;   // u00
        gt[t][2] = -cam * s2; gt[t][3] =  sam * s2;   // u01
        gt[t][4] =  cam * s2; gt[t][5] =  sam * s2;   // u10
        gt[t][6] =  cap * c2; gt[t][7] = -sap * c2;   // u11
    }
    __syncthreads();

    const int lane = t & 31;
    const int col  = blockIdx.x * 8 + (t >> 5);

    float2 s0 = make_float2((2 * lane     == col) ? 1.f : 0.f, 0.f);
    float2 s1 = make_float2((2 * lane + 1 == col) ? 1.f : 0.f, 0.f);

    for (int rep = 0; rep < 2; rep++) {
        for (int l = 0; l < 2; l++) {
            for (int q = 0; q < N_QUBITS; q++) {
                const float* g = gt[l * 6 + q];
                float2 u00 = {g[0], g[1]}, u01 = {g[2], g[3]};
                float2 u10 = {g[4], g[5]}, u11 = {g[6], g[7]};
                int m = 1 << (5 - q);
                if (m == 1) {
                    float2 a = s0, b = s1;
                    s0 = cmad(u00, a, u01, b);
                    s1 = cmad(u10, a, u11, b);
                } else {
                    int d = m >> 1;
                    float2 p0, p1;
                    p0.x = __shfl_xor_sync(0xffffffffu, s0.x, d);
                    p0.y = __shfl_xor_sync(0xffffffffu, s0.y, d);
                    p1.x = __shfl_xor_sync(0xffffffffu, s1.x, d);
                    p1.y = __shfl_xor_sync(0xffffffffu, s1.y, d);
                    if (lane & d) {
                        s0 = cmad(u10, p0, u11, s0);
                        s1 = cmad(u10, p1, u11, s1);
                    } else {
                        s0 = cmad(u00, s0, u01, p0);
                        s1 = cmad(u00, s1, u01, p1);
                    }
                }
            }
            int r = l + 1;
            for (int q = 0; q < N_QUBITS; q++) {
                int tq = (q + r) % N_QUBITS;
                int mc = 1 << (5 - q);
                int mt = 1 << (5 - tq);
                if (mt == 1) {
                    if (lane & (mc >> 1)) { float2 tmp = s0; s0 = s1; s1 = tmp; }
                } else {
                    int d = mt >> 1;
                    if (mc == 1) {
                        float2 t1;
                        t1.x = __shfl_xor_sync(0xffffffffu, s1.x, d);
                        t1.y = __shfl_xor_sync(0xffffffffu, s1.y, d);
                        s1 = t1;
                    } else {
                        float2 t0, t1;
                        t0.x = __shfl_xor_sync(0xffffffffu, s0.x, d);
                        t0.y = __shfl_xor_sync(0xffffffffu, s0.y, d);
                        t1.x = __shfl_xor_sync(0xffffffffu, s1.x, d);
                        t1.y = __shfl_xor_sync(0xffffffffu, s1.y, d);
                        if (lane & (mc >> 1)) { s0 = t0; s1 = t1; }
                    }
                }
            }
        }
    }
    g_B[(4 * lane + 0) * 64 + col] = __float2half(s0.x);
    g_B[(4 * lane + 1) * 64 + col] = __float2half(s0.y);
    g_B[(4 * lane + 2) * 64 + col] = __float2half(s1.x);
    g_B[(4 * lane + 3) * 64 + col] = __float2half(s1.y);
}

// ----------------------------------------------------------------------------
// Kernel 2: HMMA GEMM + epilogue. 128 threads (4 warps, 2x2 tile grid),
// 64 patches per CTA, 4 CTAs/SM.
// ----------------------------------------------------------------------------
#define SM_A  0            //  8 KB: 64 rows x 128 B
#define SM_B  8192         // 16 KB
#define SM_SSQ 24576       // float[64] = 256 B
#define SM_SZ  24832       // float[2][64][6] = 3072 B
#define SM_TOTAL 27904

__global__ __launch_bounds__(128, 4)
void qconv_kernel(const float* __restrict__ x, float* __restrict__ out) {
    extern __shared__ char smem[];
    const uint32_t sb = smem_u32(smem);
    float* sSsq = reinterpret_cast<float*>(smem + SM_SSQ);
    float* sZ   = reinterpret_cast<float*>(smem + SM_SZ);   // [ni][row][6]
    const int tid = threadIdx.x;

    // ---- B gmem loads first (latency overlaps x gather) ----
    uint4 breg[8];
    {
        const uint4* bsrc = reinterpret_cast<const uint4*>(g_B);
        #pragma unroll
        for (int it = 0; it < 8; it++) breg[it] = bsrc[tid + it * 128];
    }

    // ---- load phase: thread = (patch p = tid>>1, half h = tid&1 -> 2 channels)
    {
        const int p  = tid >> 1;              // 0..63
        const int h  = tid & 1;
        const int pi = blockIdx.x * 64 + p;
        const int b   = pi / OHW;
        const int rem = pi - b * OHW;
        const int oy  = rem / OH;
        const int ox  = rem - oy * OH;
        const float* xb = x + (((b * 4 + 2 * h) * 128) + 2 * oy) * 128 + 2 * ox;

        float ssq = 0.f;
        #pragma unroll
        for (int c2 = 0; c2 < 2; c2++) {
            #pragma unroll
            for (int ky2 = 0; ky2 < 2; ky2++) {
                const float* rA = xb + c2 * 16384 + (2 * ky2) * 128;
                float2 P[4];
                P[0] = *reinterpret_cast<const float2*>(rA);
                P[1] = *reinterpret_cast<const float2*>(rA + 2);
                P[2] = *reinterpret_cast<const float2*>(rA + 128);
                P[3] = *reinterpret_cast<const float2*>(rA + 130);
                uint32_t hw[4];
                #pragma unroll
                for (int j = 0; j < 4; j++) {
                    ssq += P[j].x * P[j].x + P[j].y * P[j].y;
                    __half2 h2 = __float22half2_rn(P[j]);
                    hw[j] = *reinterpret_cast<uint32_t*>(&h2);
                }
                int chunk = h * 4 + c2 * 2 + ky2;
                uint32_t off = SWZ((uint32_t)(p * 128 + chunk * 16));
                *reinterpret_cast<uint4*>(smem + SM_A + off) = make_uint4(hw[0], hw[1], hw[2], hw[3]);
            }
        }
        ssq += __shfl_xor_sync(0xffffffffu, ssq, 1);
        if (h == 0) sSsq[p] = ssq;
    }

    // ---- stage B (fp16) with swizzle ----
    {
        #pragma unroll
        for (int it = 0; it < 8; it++) {
            uint32_t off = SWZ((uint32_t)((tid + it * 128) * 16));
            *reinterpret_cast<uint4*>(smem + SM_B + off) = breg[it];
        }
    }
    __syncthreads();

    // ---- GEMM: warp (mi,ni): rows [32mi,32mi+32), cols [64ni,64ni+64) ----
    const int L   = tid & 31;
    const int wid = tid >> 5;
    const int mi  = wid >> 1;          // 0..1
    const int ni  = wid & 1;           // 0..1
    const int Rm  = mi * 32;
    const int Cn  = ni * 64;
    const int g   = L >> 2;
    const int qd  = L & 3;

    const uint32_t aRow = (uint32_t)(Rm + (L & 7) + (((L >> 3) & 1) << 3));
    const uint32_t aCh  = (L >> 4) & 1;
    const uint32_t bRow = (uint32_t)(Cn + (L & 7) + (((L >> 4) & 1) << 3));
    const uint32_t bCh  = (L >> 3) & 1;

    float acc[2][8][4];
    #pragma unroll
    for (int mt = 0; mt < 2; mt++)
        #pragma unroll
        for (int nt = 0; nt < 8; nt++)
            #pragma unroll
            for (int r = 0; r < 4; r++) acc[mt][nt][r] = 0.f;

    #pragma unroll
    for (int k = 0; k < 4; k++) {
        uint32_t ah[2][4];
        #pragma unroll
        for (int mt = 0; mt < 2; mt++) {
            uint32_t off = SWZ((aRow + mt * 16) * 128 + (2 * k + aCh) * 16);
            ldmx4(ah[mt], sb + SM_A + off);
        }
        #pragma unroll
        for (int bt = 0; bt < 4; bt++) {
            uint32_t off = SWZ((bRow + bt * 16) * 128 + (2 * k + bCh) * 16);
            uint32_t bf[4];
            ldmx4(bf, sb + SM_B + off);
            #pragma unroll
            for (int mt = 0; mt < 2; mt++)
                #pragma unroll
                for (int n2 = 0; n2 < 2; n2++) {
                    int nt = bt * 2 + n2;
                    mma_f16(acc[mt][nt], ah[mt], bf + 2 * n2);
                }
        }
    }

    // ---- epilogue: per thread 4 rows; state s = 32ni + 4nt + qd ----
    #pragma unroll
    for (int mt = 0; mt < 2; mt++) {
        #pragma unroll
        for (int rh = 0; rh < 2; rh++) {
            float pr[8];
            #pragma unroll
            for (int nt = 0; nt < 8; nt++) {
                float re = acc[mt][nt][rh * 2 + 0];
                float im = acc[mt][nt][rh * 2 + 1];
                pr[nt] = re * re + im * im;
            }
            float e0 = pr[0] + pr[4], e1 = pr[1] + pr[5];
            float e2 = pr[2] + pr[6], e3 = pr[3] + pr[7];
            float d0 = pr[0] - pr[4], d1 = pr[1] - pr[5];
            float d2 = pr[2] - pr[6], d3 = pr[3] - pr[7];
            float z1 = (d0 + d1) + (d2 + d3);
            float f0 = e0 + e2, f1 = e1 + e3;
            float qt = f0 + f1;
            float z3 = f0 - f1;
            float z2 = (e0 - e2) + (e1 - e3);

            float W = qt;
            #pragma unroll
            for (int m = 1; m <= 2; m <<= 1) {
                float tt = __shfl_xor_sync(0xffffffffu, W, m);
                W = (L & m) ? (tt - W) : (W + tt);
            }
            z1 += __shfl_xor_sync(0xffffffffu, z1, 1);
            z1 += __shfl_xor_sync(0xffffffffu, z1, 2);
            z2 += __shfl_xor_sync(0xffffffffu, z2, 1);
            z2 += __shfl_xor_sync(0xffffffffu, z2, 2);
            z3 += __shfl_xor_sync(0xffffffffu, z3, 1);
            z3 += __shfl_xor_sync(0xffffffffu, z3, 2);

            int row = Rm + mt * 16 + rh * 8 + g;
            float* dst = sZ + (ni * 64 + row) * 6;
            if (qd == 0) { dst[0] = W; dst[1] = z1; dst[2] = z2; dst[3] = z3; }
            else if (qd == 1) dst[5] = W;
            else if (qd == 2) dst[4] = W;
        }
    }
    __syncthreads();

    // ---- merge halves + normalize + store (384 outputs, 128 threads) ----
    #pragma unroll
    for (int half = 0; half < 3; half++) {
        int idx = tid + half * 128;
        int qb  = idx >> 6;            // 0..5
        int row = idx & 63;
        int pi  = blockIdx.x * 64 + row;
        int b   = pi / OHW;
        int rem = pi - b * OHW;
        float inv = 1.f / sSsq[row];
        float a0 = sZ[row * 6 + qb];
        float a1 = sZ[(64 + row) * 6 + qb];
        float zv = (qb == 0) ? (a0 - a1) : (a0 + a1);
        out[(b * 6 + qb) * OHW + rem] = zv * inv;
    }
}

// ----------------------------------------------------------------------------
extern "C" void kernel_launch(void* const* d_in, const int* in_sizes, int n_in,
                              void* d_out, int out_size) {
    const float* x = (const float*)d_in[0];      // (128, 4, 128, 128) f32
    const float* w = (const float*)d_in[1];      // (2, 6, 3) f32
    float* out = (float*)d_out;                  // (128, 6, 63, 63) f32
    (void)in_sizes; (void)n_in; (void)out_size;

    cudaFuncSetAttribute(qconv_kernel, cudaFuncAttributeMaxDynamicSharedMemorySize, SM_TOTAL);
    build_unitary_kernel<<<8, 256>>>(w);
    qconv_kernel<<<NPATCH / 64, 128, SM_TOTAL>>>(x, out);
}

// round 12
// speedup vs baseline: 1.2068x; 1.0731x over previous
#include <cuda_runtime.h>
#include <cuda_fp16.h>
#include <cstdint>

// ============================================================================
// QConv2D quantum conv via baseline-PTX fp16 mma.sync (HMMA) GEMM.
//   Kernel 1: build 64x64 unitary U (register statevector, warp per column).
//   B[128x64] fp16, rows interleaved: B[2s]=Re U[s,:], B[2s+1]=Im U[s,:].
//   Kernel 2 (CTA = 64 patches, 128 threads, 5 CTAs/SM): B staged by cp.async
//   (no registers), A = patch fp16, C[64x128] = A*B^T (fp32 accum).
//   Epilogue: probs, factorized Walsh, deferred normalization by ||f||^2.
// ============================================================================

#define N_QUBITS 6
#define OH 63
#define OHW 3969
#define NPATCH (128 * OHW)     // 508032
#define SWZ(o) ((o) ^ (((o) >> 3) & 0x70))

__device__ __half g_B[128 * 64];

__device__ __forceinline__ uint32_t smem_u32(const void* p) {
    uint32_t a;
    asm("{ .reg .u64 t; cvta.to.shared.u64 t, %1; cvt.u32.u64 %0, t; }"
        : "=r"(a) : "l"(p));
    return a;
}
__device__ __forceinline__ void ldmx4(uint32_t* r, uint32_t addr) {
    asm volatile("ldmatrix.sync.aligned.m8n8.x4.shared.b16 {%0,%1,%2,%3}, [%4];"
                 : "=r"(r[0]), "=r"(r[1]), "=r"(r[2]), "=r"(r[3]) : "r"(addr));
}
__device__ __forceinline__ void mma_f16(float* c, const uint32_t* a, const uint32_t* b) {
    asm volatile(
        "mma.sync.aligned.m16n8k16.row.col.f32.f16.f16.f32 "
        "{%0,%1,%2,%3}, {%4,%5,%6,%7}, {%8,%9}, {%0,%1,%2,%3};"
        : "+f"(c[0]), "+f"(c[1]), "+f"(c[2]), "+f"(c[3])
        : "r"(a[0]), "r"(a[1]), "r"(a[2]), "r"(a[3]), "r"(b[0]), "r"(b[1]));
}
#define CP_ASYNC16(dst, src) \
    asm volatile("cp.async.ca.shared.global [%0], [%1], 16;" :: "r"(dst), "l"(src) : "memory")
#define CP_COMMIT() asm volatile("cp.async.commit_group;" ::: "memory")
#define CP_WAIT0()  asm volatile("cp.async.wait_group 0;" ::: "memory")

__device__ __forceinline__ float2 cmad(float2 u, float2 a, float2 v, float2 b) {
    float2 r;
    r.x = u.x * a.x - u.y * a.y + v.x * b.x - v.y * b.y;
    r.y = u.x * a.y + u.y * a.x + v.x * b.y + v.y * b.x;
    return r;
}

// ----------------------------------------------------------------------------
// Kernel 1: build U. One warp per column; lane holds states 2L, 2L+1.
// ----------------------------------------------------------------------------
__global__ __launch_bounds__(256) void build_unitary_kernel(const float* __restrict__ w) {
    __shared__ float gt[12][8];
    const int t = threadIdx.x;
    if (t < 12) {
        int l = t / 6, q = t % 6;
        float phi   = w[(l * 6 + q) * 3 + 0];
        float theta = w[(l * 6 + q) * 3 + 1];
        float omega = w[(l * 6 + q) * 3 + 2];
        float s2, c2; sincosf(0.5f * theta, &s2, &c2);
        float sap, cap; sincosf(-0.5f * (phi + omega), &sap, &cap);
        float sam, cam; sincosf(-0.5f * (phi - omega), &sam, &cam);
        gt[t][0] =  cap * c2; gt[t][1] =  sap * c2;   // u00
        gt[t][2] = -cam * s2; gt[t][3] =  sam * s2;   // u01
        gt[t][4] =  cam * s2; gt[t][5] =  sam * s2;   // u10
        gt[t][6] =  cap * c2; gt[t][7] = -sap * c2;   // u11
    }
    __syncthreads();

    const int lane = t & 31;
    const int col  = blockIdx.x * 8 + (t >> 5);

    float2 s0 = make_float2((2 * lane     == col) ? 1.f : 0.f, 0.f);
    float2 s1 = make_float2((2 * lane + 1 == col) ? 1.f : 0.f, 0.f);

    for (int rep = 0; rep < 2; rep++) {
        for (int l = 0; l < 2; l++) {
            for (int q = 0; q < N_QUBITS; q++) {
                const float* g = gt[l * 6 + q];
                float2 u00 = {g[0], g[1]}, u01 = {g[2], g[3]};
                float2 u10 = {g[4], g[5]}, u11 = {g[6], g[7]};
                int m = 1 << (5 - q);
                if (m == 1) {
                    float2 a = s0, b = s1;
                    s0 = cmad(u00, a, u01, b);
                    s1 = cmad(u10, a, u11, b);
                } else {
                    int d = m >> 1;
                    float2 p0, p1;
                    p0.x = __shfl_xor_sync(0xffffffffu, s0.x, d);
                    p0.y = __shfl_xor_sync(0xffffffffu, s0.y, d);
                    p1.x = __shfl_xor_sync(0xffffffffu, s1.x, d);
                    p1.y = __shfl_xor_sync(0xffffffffu, s1.y, d);
                    if (lane & d) {
                        s0 = cmad(u10, p0, u11, s0);
                        s1 = cmad(u10, p1, u11, s1);
                    } else {
                        s0 = cmad(u00, s0, u01, p0);
                        s1 = cmad(u00, s1, u01, p1);
                    }
                }
            }
            int r = l + 1;
            for (int q = 0; q < N_QUBITS; q++) {
                int tq = (q + r) % N_QUBITS;
                int mc = 1 << (5 - q);
                int mt = 1 << (5 - tq);
                if (mt == 1) {
                    if (lane & (mc >> 1)) { float2 tmp = s0; s0 = s1; s1 = tmp; }
                } else {
                    int d = mt >> 1;
                    if (mc == 1) {
                        float2 t1;
                        t1.x = __shfl_xor_sync(0xffffffffu, s1.x, d);
                        t1.y = __shfl_xor_sync(0xffffffffu, s1.y, d);
                        s1 = t1;
                    } else {
                        float2 t0, t1;
                        t0.x = __shfl_xor_sync(0xffffffffu, s0.x, d);
                        t0.y = __shfl_xor_sync(0xffffffffu, s0.y, d);
                        t1.x = __shfl_xor_sync(0xffffffffu, s1.x, d);
                        t1.y = __shfl_xor_sync(0xffffffffu, s1.y, d);
                        if (lane & (mc >> 1)) { s0 = t0; s1 = t1; }
                    }
                }
            }
        }
    }
    g_B[(4 * lane + 0) * 64 + col] = __float2half(s0.x);
    g_B[(4 * lane + 1) * 64 + col] = __float2half(s0.y);
    g_B[(4 * lane + 2) * 64 + col] = __float2half(s1.x);
    g_B[(4 * lane + 3) * 64 + col] = __float2half(s1.y);
}

// ----------------------------------------------------------------------------
// Kernel 2: HMMA GEMM + epilogue. 128 threads (4 warps, 2x2 tile grid),
// 64 patches per CTA, 5 CTAs/SM. B staged by cp.async (register-free).
// ----------------------------------------------------------------------------
#define SM_A  0            //  8 KB: 64 rows x 128 B
#define SM_B  8192         // 16 KB
#define SM_SSQ 24576       // float[64] = 256 B
#define SM_SZ  24832       // float[2][64][6] = 3072 B
#define SM_TOTAL 27904

__global__ __launch_bounds__(128, 5)
void qconv_kernel(const float* __restrict__ x, float* __restrict__ out) {
    extern __shared__ char smem[];
    const uint32_t sb = smem_u32(smem);
    float* sSsq = reinterpret_cast<float*>(smem + SM_SSQ);
    float* sZ   = reinterpret_cast<float*>(smem + SM_SZ);   // [ni][row][6]
    const int tid = threadIdx.x;

    // ---- async-stage B gmem -> smem (swizzled), zero register cost ----
    {
        const char* bsrc = reinterpret_cast<const char*>(g_B);
        #pragma unroll
        for (int it = 0; it < 8; it++) {
            int idx = tid + it * 128;
            uint32_t off = SWZ((uint32_t)(idx * 16));
            CP_ASYNC16(sb + SM_B + off, bsrc + idx * 16);
        }
        CP_COMMIT();
    }

    // ---- load phase: thread = (patch p = tid>>1, half h = tid&1 -> 2 channels)
    {
        const int p  = tid >> 1;              // 0..63
        const int h  = tid & 1;
        const int pi = blockIdx.x * 64 + p;
        const int b   = pi / OHW;
        const int rem = pi - b * OHW;
        const int oy  = rem / OH;
        const int ox  = rem - oy * OH;
        const float* xb = x + (((b * 4 + 2 * h) * 128) + 2 * oy) * 128 + 2 * ox;

        float ssq = 0.f;
        #pragma unroll
        for (int c2 = 0; c2 < 2; c2++) {
            #pragma unroll
            for (int ky2 = 0; ky2 < 2; ky2++) {
                const float* rA = xb + c2 * 16384 + (2 * ky2) * 128;
                float2 P[4];
                P[0] = *reinterpret_cast<const float2*>(rA);
                P[1] = *reinterpret_cast<const float2*>(rA + 2);
                P[2] = *reinterpret_cast<const float2*>(rA + 128);
                P[3] = *reinterpret_cast<const float2*>(rA + 130);
                uint32_t hw[4];
                #pragma unroll
                for (int j = 0; j < 4; j++) {
                    ssq += P[j].x * P[j].x + P[j].y * P[j].y;
                    __half2 h2 = __float22half2_rn(P[j]);
                    hw[j] = *reinterpret_cast<uint32_t*>(&h2);
                }
                int chunk = h * 4 + c2 * 2 + ky2;
                uint32_t off = SWZ((uint32_t)(p * 128 + chunk * 16));
                *reinterpret_cast<uint4*>(smem + SM_A + off) = make_uint4(hw[0], hw[1], hw[2], hw[3]);
            }
        }
        ssq += __shfl_xor_sync(0xffffffffu, ssq, 1);
        if (h == 0) sSsq[p] = ssq;
    }

    CP_WAIT0();              // B staged
    __syncthreads();

    // ---- GEMM: warp (mi,ni): rows [32mi,32mi+32), cols [64ni,64ni+64) ----
    const int L   = tid & 31;
    const int wid = tid >> 5;
    const int mi  = wid >> 1;          // 0..1
    const int ni  = wid & 1;           // 0..1
    const int Rm  = mi * 32;
    const int Cn  = ni * 64;
    const int g   = L >> 2;
    const int qd  = L & 3;

    const uint32_t aRow = (uint32_t)(Rm + (L & 7) + (((L >> 3) & 1) << 3));
    const uint32_t aCh  = (L >> 4) & 1;
    const uint32_t bRow = (uint32_t)(Cn + (L & 7) + (((L >> 4) & 1) << 3));
    const uint32_t bCh  = (L >> 3) & 1;

    float acc[2][8][4];
    #pragma unroll
    for (int mt = 0; mt < 2; mt++)
        #pragma unroll
        for (int nt = 0; nt < 8; nt++)
            #pragma unroll
            for (int r = 0; r < 4; r++) acc[mt][nt][r] = 0.f;

    #pragma unroll
    for (int k = 0; k < 4; k++) {
        uint32_t ah[2][4];
        #pragma unroll
        for (int mt = 0; mt < 2; mt++) {
            uint32_t off = SWZ((aRow + mt * 16) * 128 + (2 * k + aCh) * 16);
            ldmx4(ah[mt], sb + SM_A + off);
        }
        #pragma unroll
        for (int bt = 0; bt < 4; bt++) {
            uint32_t off = SWZ((bRow + bt * 16) * 128 + (2 * k + bCh) * 16);
            uint32_t bf[4];
            ldmx4(bf, sb + SM_B + off);
            #pragma unroll
            for (int mt = 0; mt < 2; mt++)
                #pragma unroll
                for (int n2 = 0; n2 < 2; n2++) {
                    int nt = bt * 2 + n2;
                    mma_f16(acc[mt][nt], ah[mt], bf + 2 * n2);
                }
        }
    }

    // ---- epilogue: per thread 4 rows; state s = 32ni + 4nt + qd ----
    #pragma unroll
    for (int mt = 0; mt < 2; mt++) {
        #pragma unroll
        for (int rh = 0; rh < 2; rh++) {
            float pr[8];
            #pragma unroll
            for (int nt = 0; nt < 8; nt++) {
                float re = acc[mt][nt][rh * 2 + 0];
                float im = acc[mt][nt][rh * 2 + 1];
                pr[nt] = re * re + im * im;
            }
            float e0 = pr[0] + pr[4], e1 = pr[1] + pr[5];
            float e2 = pr[2] + pr[6], e3 = pr[3] + pr[7];
            float d0 = pr[0] - pr[4], d1 = pr[1] - pr[5];
            float d2 = pr[2] - pr[6], d3 = pr[3] - pr[7];
            float z1 = (d0 + d1) + (d2 + d3);
            float f0 = e0 + e2, f1 = e1 + e3;
            float qt = f0 + f1;
            float z3 = f0 - f1;
            float z2 = (e0 - e2) + (e1 - e3);

            float W = qt;
            #pragma unroll
            for (int m = 1; m <= 2; m <<= 1) {
                float tt = __shfl_xor_sync(0xffffffffu, W, m);
                W = (L & m) ? (tt - W) : (W + tt);
            }
            z1 += __shfl_xor_sync(0xffffffffu, z1, 1);
            z1 += __shfl_xor_sync(0xffffffffu, z1, 2);
            z2 += __shfl_xor_sync(0xffffffffu, z2, 1);
            z2 += __shfl_xor_sync(0xffffffffu, z2, 2);
            z3 += __shfl_xor_sync(0xffffffffu, z3, 1);
            z3 += __shfl_xor_sync(0xffffffffu, z3, 2);

            int row = Rm + mt * 16 + rh * 8 + g;
            float* dst = sZ + (ni * 64 + row) * 6;
            if (qd == 0) { dst[0] = W; dst[1] = z1; dst[2] = z2; dst[3] = z3; }
            else if (qd == 1) dst[5] = W;
            else if (qd == 2) dst[4] = W;
        }
    }
    __syncthreads();

    // ---- merge halves + normalize + store (384 outputs, 128 threads) ----
    #pragma unroll
    for (int half = 0; half < 3; half++) {
        int idx = tid + half * 128;
        int qb  = idx >> 6;            // 0..5
        int row = idx & 63;
        int pi  = blockIdx.x * 64 + row;
        int b   = pi / OHW;
        int rem = pi - b * OHW;
        float inv = 1.f / sSsq[row];
        float a0 = sZ[row * 6 + qb];
        float a1 = sZ[(64 + row) * 6 + qb];
        float zv = (qb == 0) ? (a0 - a1) : (a0 + a1);
        out[(b * 6 + qb) * OHW + rem] = zv * inv;
    }
}

// ----------------------------------------------------------------------------
extern "C" void kernel_launch(void* const* d_in, const int* in_sizes, int n_in,
                              void* d_out, int out_size) {
    const float* x = (const float*)d_in[0];      // (128, 4, 128, 128) f32
    const float* w = (const float*)d_in[1];      // (2, 6, 3) f32
    float* out = (float*)d_out;                  // (128, 6, 63, 63) f32
    (void)in_sizes; (void)n_in; (void)out_size;

    cudaFuncSetAttribute(qconv_kernel, cudaFuncAttributeMaxDynamicSharedMemorySize, SM_TOTAL);
    build_unitary_kernel<<<8, 256>>>(w);
    qconv_kernel<<<NPATCH / 64, 128, SM_TOTAL>>>(x, out);
}